// round 2
// baseline (speedup 1.0000x reference)
#include <cuda_runtime.h>

#define S_LEN 2048
#define DMODEL 1024
#define NHEAD 16
#define HSZ 64
#define N3 (3 * DMODEL)

// Scratch (no allocations allowed): qkv [S, 3D] = 24 MB, attn out [S, D] = 8 MB
__device__ float g_qkv[S_LEN * N3];
__device__ float g_att[S_LEN * DMODEL];

// ---------------------------------------------------------------------------
// SGEMM: C[M,N] = A[M,K] @ B[K,N] + bias[N]
// BM=BN=128, BK=8, 256 threads, 8x8 per-thread microtile.
// M % 128 == 0, N % 128 == 0, K % 8 == 0 (true for all our shapes).
// ---------------------------------------------------------------------------
template <int M, int N, int K>
__global__ __launch_bounds__(256)
void sgemm_bias(const float* __restrict__ A, const float* __restrict__ B,
                const float* __restrict__ bias, float* __restrict__ C) {
    constexpr int BM = 128, BN = 128, BK = 8;
    __shared__ __align__(16) float As[BK][BM];
    __shared__ __align__(16) float Bs[BK][BN];

    const int tid = threadIdx.x;
    const int bx = blockIdx.x, by = blockIdx.y;
    const int tx = tid % 16, ty = tid / 16;

    // A tile load: 128 rows x 8 k -> 4 floats per thread (float4)
    const int arow = tid >> 1;            // 0..127
    const int acol = (tid & 1) * 4;       // 0 or 4
    // B tile load: 8 rows x 128 cols -> float4 per thread
    const int brow = tid >> 5;            // 0..7
    const int bcol = (tid & 31) * 4;      // 0..124

    const float* Ab = A + (size_t)(by * BM) * K;
    const float* Bb = B + bx * BN;

    float c[8][8];
#pragma unroll
    for (int i = 0; i < 8; i++)
#pragma unroll
        for (int j = 0; j < 8; j++) c[i][j] = 0.f;

    for (int k0 = 0; k0 < K; k0 += BK) {
        float4 av = *(const float4*)(Ab + (size_t)arow * K + k0 + acol);
        As[acol + 0][arow] = av.x;
        As[acol + 1][arow] = av.y;
        As[acol + 2][arow] = av.z;
        As[acol + 3][arow] = av.w;
        *(float4*)&Bs[brow][bcol] =
            *(const float4*)(Bb + (size_t)(k0 + brow) * N + bcol);
        __syncthreads();

#pragma unroll
        for (int k = 0; k < BK; k++) {
            float a[8], b[8];
            float4 a0 = *(const float4*)&As[k][ty * 8];
            float4 a1 = *(const float4*)&As[k][ty * 8 + 4];
            float4 b0 = *(const float4*)&Bs[k][tx * 8];
            float4 b1 = *(const float4*)&Bs[k][tx * 8 + 4];
            a[0] = a0.x; a[1] = a0.y; a[2] = a0.z; a[3] = a0.w;
            a[4] = a1.x; a[5] = a1.y; a[6] = a1.z; a[7] = a1.w;
            b[0] = b0.x; b[1] = b0.y; b[2] = b0.z; b[3] = b0.w;
            b[4] = b1.x; b[5] = b1.y; b[6] = b1.z; b[7] = b1.w;
#pragma unroll
            for (int i = 0; i < 8; i++)
#pragma unroll
                for (int j = 0; j < 8; j++)
                    c[i][j] = fmaf(a[i], b[j], c[i][j]);
        }
        __syncthreads();
    }

    // Epilogue: add bias, store
#pragma unroll
    for (int i = 0; i < 8; i++) {
        const size_t row = (size_t)(by * BM + ty * 8 + i);
        const int colbase = bx * BN + tx * 8;
        float4 v0, v1;
        v0.x = c[i][0] + bias[colbase + 0];
        v0.y = c[i][1] + bias[colbase + 1];
        v0.z = c[i][2] + bias[colbase + 2];
        v0.w = c[i][3] + bias[colbase + 3];
        v1.x = c[i][4] + bias[colbase + 4];
        v1.y = c[i][5] + bias[colbase + 5];
        v1.z = c[i][6] + bias[colbase + 6];
        v1.w = c[i][7] + bias[colbase + 7];
        *(float4*)(C + row * N + colbase) = v0;
        *(float4*)(C + row * N + colbase + 4) = v1;
    }
}

// ---------------------------------------------------------------------------
// Flash-style causal attention over g_qkv, writes g_att.
// One thread = one query row (q[64], acc[64] in registers).
// Block: 128 threads = 128 query rows of one head; K/V tiles 64x64 in smem.
// grid = (S/128, H)
// ---------------------------------------------------------------------------
__global__ __launch_bounds__(128)
void attn_kernel() {
    constexpr int ROWS = 128, TN = 64;
    __shared__ __align__(16) float Ks[TN][HSZ];
    __shared__ __align__(16) float Vs[TN][HSZ];

    const int h = blockIdx.y;
    const int r = blockIdx.x * ROWS + threadIdx.x;
    const float scale = rsqrtf((float)S_LEN);  // NOTE: ref scales by sqrt(S)

    float q[HSZ], acc[HSZ];
    const float* qrow = g_qkv + (size_t)r * N3 + h * HSZ;
#pragma unroll
    for (int d = 0; d < HSZ; d++) {
        q[d] = qrow[d] * scale;
        acc[d] = 0.f;
    }
    float mmax = -1e30f, l = 0.f;

    const int kend = blockIdx.x * ROWS + ROWS;  // exclusive key bound for block
    for (int j0 = 0; j0 < kend; j0 += TN) {
        __syncthreads();
        // cooperative load: TN*HSZ floats each for K and V; 128 thr * float4
        for (int idx = threadIdx.x * 4; idx < TN * HSZ; idx += 128 * 4) {
            const int kr = idx / HSZ, kc = idx % HSZ;
            const size_t base = (size_t)(j0 + kr) * N3 + h * HSZ + kc;
            *(float4*)&Ks[kr][kc] = *(const float4*)(g_qkv + base + DMODEL);
            *(float4*)&Vs[kr][kc] = *(const float4*)(g_qkv + base + 2 * DMODEL);
        }
        __syncthreads();

        const int jend = min(TN, r - j0 + 1);  // causal
        for (int j = 0; j < jend; j++) {
            float s0 = 0.f, s1 = 0.f, s2 = 0.f, s3 = 0.f;
#pragma unroll
            for (int d = 0; d < HSZ; d += 4) {
                s0 = fmaf(q[d + 0], Ks[j][d + 0], s0);
                s1 = fmaf(q[d + 1], Ks[j][d + 1], s1);
                s2 = fmaf(q[d + 2], Ks[j][d + 2], s2);
                s3 = fmaf(q[d + 3], Ks[j][d + 3], s3);
            }
            const float s = (s0 + s1) + (s2 + s3);
            float p;
            if (s > mmax) {
                const float alpha = __expf(mmax - s);
                l *= alpha;
#pragma unroll
                for (int d = 0; d < HSZ; d++) acc[d] *= alpha;
                mmax = s;
                p = 1.f;
            } else {
                p = __expf(s - mmax);
            }
            l += p;
#pragma unroll
            for (int d = 0; d < HSZ; d++)
                acc[d] = fmaf(p, Vs[j][d], acc[d]);
        }
    }

    const float inv = 1.f / l;
    float* o = g_att + (size_t)r * DMODEL + h * HSZ;
#pragma unroll
    for (int d = 0; d < HSZ; d += 4) {
        float4 v;
        v.x = acc[d + 0] * inv;
        v.y = acc[d + 1] * inv;
        v.z = acc[d + 2] * inv;
        v.w = acc[d + 3] * inv;
        *(float4*)(o + d) = v;
    }
}

// ---------------------------------------------------------------------------
extern "C" void kernel_launch(void* const* d_in, const int* in_sizes, int n_in,
                              void* d_out, int out_size) {
    const float* hs     = (const float*)d_in[0];
    const float* W_attn = (const float*)d_in[1];
    const float* b_attn = (const float*)d_in[2];
    const float* W_proj = (const float*)d_in[3];
    const float* b_proj = (const float*)d_in[4];
    float* out = (float*)d_out;

    float *qkv, *att;
    cudaGetSymbolAddress((void**)&qkv, g_qkv);
    cudaGetSymbolAddress((void**)&att, g_att);

    // 1. QKV = hs @ W_attn + b_attn   [2048, 3072]
    {
        dim3 grid(N3 / 128, S_LEN / 128);
        sgemm_bias<S_LEN, N3, DMODEL><<<grid, 256>>>(hs, W_attn, b_attn, qkv);
    }
    // 2. Causal attention -> g_att [2048, 1024]
    {
        dim3 grid(S_LEN / 128, NHEAD);
        attn_kernel<<<grid, 128>>>();
    }
    // 3. out = att @ W_proj + b_proj  [2048, 1024]
    {
        dim3 grid(DMODEL / 128, S_LEN / 128);
        sgemm_bias<S_LEN, DMODEL, DMODEL><<<grid, 256>>>(att, W_proj, b_proj, out);
    }
}

// round 3
// speedup vs baseline: 1.1824x; 1.1824x over previous
#include <cuda_runtime.h>

#define S_LEN 2048
#define DMODEL 1024
#define NHEAD 16
#define HSZ 64
#define N3 (3 * DMODEL)

// Scratch (no allocations allowed): qkv [S, 3D] = 24 MB, attn out [S, D] = 8 MB
__device__ float g_qkv[S_LEN * N3];
__device__ float g_att[S_LEN * DMODEL];

// ---------------------------------------------------------------------------
// SGEMM: C[M,N] = A[M,K] @ B[K,N] + bias[N]
// BM=BN=128, BK=16, 256 threads, 8x8 microtile, double-buffered smem with
// global->register prefetch. One __syncthreads per 1024 FMAs/thread.
// ---------------------------------------------------------------------------
template <int N, int K>
__global__ __launch_bounds__(256)
void sgemm_bias(const float* __restrict__ A, const float* __restrict__ B,
                const float* __restrict__ bias, float* __restrict__ C) {
    constexpr int BM = 128, BN = 128, BK = 16;
    __shared__ __align__(16) float As[2][BK][BM];
    __shared__ __align__(16) float Bs[2][BK][BN];

    const int tid = threadIdx.x;
    const int bx = blockIdx.x, by = blockIdx.y;
    const int tx = tid % 16, ty = tid / 16;

    // A tile: 128 rows x 16 k -> 8 floats (2x float4) per thread
    const int arow = tid >> 1;
    const int acol = (tid & 1) * 8;
    // B tile: 16 rows x 128 cols -> 8 floats (2x float4) per thread
    const int brow = tid >> 4;
    const int bcol = (tid & 15) * 8;

    const float* Ab = A + (size_t)(by * BM) * K + (size_t)arow * K + acol;
    const float* Bb = B + (size_t)brow * N + bx * BN + bcol;

    float4 ar0, ar1, br0, br1;

    // Prologue: tile 0 -> buffer 0
    ar0 = *(const float4*)(Ab);
    ar1 = *(const float4*)(Ab + 4);
    br0 = *(const float4*)(Bb);
    br1 = *(const float4*)(Bb + 4);
    As[0][acol + 0][arow] = ar0.x;
    As[0][acol + 1][arow] = ar0.y;
    As[0][acol + 2][arow] = ar0.z;
    As[0][acol + 3][arow] = ar0.w;
    As[0][acol + 4][arow] = ar1.x;
    As[0][acol + 5][arow] = ar1.y;
    As[0][acol + 6][arow] = ar1.z;
    As[0][acol + 7][arow] = ar1.w;
    *(float4*)&Bs[0][brow][bcol] = br0;
    *(float4*)&Bs[0][brow][bcol + 4] = br1;
    __syncthreads();

    float c[8][8];
#pragma unroll
    for (int i = 0; i < 8; i++)
#pragma unroll
        for (int j = 0; j < 8; j++) c[i][j] = 0.f;

    constexpr int NT = K / BK;
    for (int t = 0; t < NT; t++) {
        const int cur = t & 1;
        // Prefetch next tile into registers (overlaps with compute below)
        if (t + 1 < NT) {
            const int k0 = (t + 1) * BK;
            ar0 = *(const float4*)(Ab + k0);
            ar1 = *(const float4*)(Ab + k0 + 4);
            br0 = *(const float4*)(Bb + (size_t)k0 * N);
            br1 = *(const float4*)(Bb + (size_t)k0 * N + 4);
        }
#pragma unroll
        for (int k = 0; k < BK; k++) {
            float a[8], b[8];
            float4 a0 = *(const float4*)&As[cur][k][ty * 8];
            float4 a1 = *(const float4*)&As[cur][k][ty * 8 + 4];
            float4 b0 = *(const float4*)&Bs[cur][k][tx * 8];
            float4 b1 = *(const float4*)&Bs[cur][k][tx * 8 + 4];
            a[0] = a0.x; a[1] = a0.y; a[2] = a0.z; a[3] = a0.w;
            a[4] = a1.x; a[5] = a1.y; a[6] = a1.z; a[7] = a1.w;
            b[0] = b0.x; b[1] = b0.y; b[2] = b0.z; b[3] = b0.w;
            b[4] = b1.x; b[5] = b1.y; b[6] = b1.z; b[7] = b1.w;
#pragma unroll
            for (int i = 0; i < 8; i++)
#pragma unroll
                for (int j = 0; j < 8; j++)
                    c[i][j] = fmaf(a[i], b[j], c[i][j]);
        }
        if (t + 1 < NT) {
            const int nxt = cur ^ 1;
            As[nxt][acol + 0][arow] = ar0.x;
            As[nxt][acol + 1][arow] = ar0.y;
            As[nxt][acol + 2][arow] = ar0.z;
            As[nxt][acol + 3][arow] = ar0.w;
            As[nxt][acol + 4][arow] = ar1.x;
            As[nxt][acol + 5][arow] = ar1.y;
            As[nxt][acol + 6][arow] = ar1.z;
            As[nxt][acol + 7][arow] = ar1.w;
            *(float4*)&Bs[nxt][brow][bcol] = br0;
            *(float4*)&Bs[nxt][brow][bcol + 4] = br1;
            __syncthreads();
        }
    }

    // Epilogue: add bias, store
#pragma unroll
    for (int i = 0; i < 8; i++) {
        const size_t row = (size_t)(by * BM + ty * 8 + i);
        const int colbase = bx * BN + tx * 8;
        float4 v0, v1;
        v0.x = c[i][0] + bias[colbase + 0];
        v0.y = c[i][1] + bias[colbase + 1];
        v0.z = c[i][2] + bias[colbase + 2];
        v0.w = c[i][3] + bias[colbase + 3];
        v1.x = c[i][4] + bias[colbase + 4];
        v1.y = c[i][5] + bias[colbase + 5];
        v1.z = c[i][6] + bias[colbase + 6];
        v1.w = c[i][7] + bias[colbase + 7];
        *(float4*)(C + row * N + colbase) = v0;
        *(float4*)(C + row * N + colbase + 4) = v1;
    }
}

// ---------------------------------------------------------------------------
// Flash-style causal attention over g_qkv, writes g_att.
// One thread = one query row (q[64], acc[64], s[32] in registers).
// Two-phase per 32-key tile: (1) all 32 scores (pure FMA, high ILP),
// (2) tile-max + one batched rescale + batched exp + P.V accumulation.
// Block: 128 threads = 128 query rows of one head. grid = (S/128, H)
// ---------------------------------------------------------------------------
__global__ __launch_bounds__(128)
void attn_kernel() {
    constexpr int ROWS = 128, TN = 32;
    __shared__ __align__(16) float Ks[TN][HSZ];
    __shared__ __align__(16) float Vs[TN][HSZ];

    const int h = blockIdx.y;
    const int r = blockIdx.x * ROWS + threadIdx.x;
    const float scale = rsqrtf((float)S_LEN);  // ref scales by sqrt(S)

    float q[HSZ], acc[HSZ], s[TN];
    const float* qrow = g_qkv + (size_t)r * N3 + h * HSZ;
#pragma unroll
    for (int d = 0; d < HSZ; d++) {
        q[d] = qrow[d] * scale;
        acc[d] = 0.f;
    }
    float mmax = -1e30f, l = 0.f;

    const int kend = blockIdx.x * ROWS + ROWS;  // exclusive key bound
    for (int j0 = 0; j0 < kend; j0 += TN) {
        __syncthreads();
        // cooperative load of K/V tile: TN*HSZ floats each (128 thr * float4)
#pragma unroll
        for (int it = 0; it < (TN * HSZ) / (128 * 4); it++) {
            const int idx = threadIdx.x * 4 + it * 128 * 4;
            const int kr = idx / HSZ, kc = idx % HSZ;
            const size_t base = (size_t)(j0 + kr) * N3 + h * HSZ + kc;
            *(float4*)&Ks[kr][kc] = *(const float4*)(g_qkv + base + DMODEL);
            *(float4*)&Vs[kr][kc] = *(const float4*)(g_qkv + base + 2 * DMODEL);
        }
        __syncthreads();

        const int jend = min(TN, r - j0 + 1);  // causal (may be <= 0)

        // Phase 1: scores for all TN keys (pure FMA)
#pragma unroll
        for (int j = 0; j < TN; j++) {
            float s0 = 0.f, s1 = 0.f, s2 = 0.f, s3 = 0.f;
            const float4* k4 = (const float4*)Ks[j];
#pragma unroll
            for (int d4 = 0; d4 < HSZ / 4; d4++) {
                float4 kv = k4[d4];
                s0 = fmaf(q[d4 * 4 + 0], kv.x, s0);
                s1 = fmaf(q[d4 * 4 + 1], kv.y, s1);
                s2 = fmaf(q[d4 * 4 + 2], kv.z, s2);
                s3 = fmaf(q[d4 * 4 + 3], kv.w, s3);
            }
            s[j] = (s0 + s1) + (s2 + s3);
        }
        // Causal mask
#pragma unroll
        for (int j = 0; j < TN; j++)
            if (j >= jend) s[j] = -1e30f;

        // Phase 2: tile max, single rescale, exp, P.V
        float tm = mmax;
#pragma unroll
        for (int j = 0; j < TN; j++) tm = fmaxf(tm, s[j]);
        const float alpha = __expf(mmax - tm);
        mmax = tm;
        l *= alpha;
#pragma unroll
        for (int d = 0; d < HSZ; d++) acc[d] *= alpha;

#pragma unroll
        for (int j = 0; j < TN; j++) {
            const float p = __expf(s[j] - mmax);
            l += p;
            const float4* v4 = (const float4*)Vs[j];
#pragma unroll
            for (int d4 = 0; d4 < HSZ / 4; d4++) {
                float4 vv = v4[d4];
                acc[d4 * 4 + 0] = fmaf(p, vv.x, acc[d4 * 4 + 0]);
                acc[d4 * 4 + 1] = fmaf(p, vv.y, acc[d4 * 4 + 1]);
                acc[d4 * 4 + 2] = fmaf(p, vv.z, acc[d4 * 4 + 2]);
                acc[d4 * 4 + 3] = fmaf(p, vv.w, acc[d4 * 4 + 3]);
            }
        }
    }

    const float inv = 1.f / l;
    float* o = g_att + (size_t)r * DMODEL + h * HSZ;
#pragma unroll
    for (int d = 0; d < HSZ; d += 4) {
        float4 v;
        v.x = acc[d + 0] * inv;
        v.y = acc[d + 1] * inv;
        v.z = acc[d + 2] * inv;
        v.w = acc[d + 3] * inv;
        *(float4*)(o + d) = v;
    }
}

// ---------------------------------------------------------------------------
extern "C" void kernel_launch(void* const* d_in, const int* in_sizes, int n_in,
                              void* d_out, int out_size) {
    const float* hs     = (const float*)d_in[0];
    const float* W_attn = (const float*)d_in[1];
    const float* b_attn = (const float*)d_in[2];
    const float* W_proj = (const float*)d_in[3];
    const float* b_proj = (const float*)d_in[4];
    float* out = (float*)d_out;

    float *qkv, *att;
    cudaGetSymbolAddress((void**)&qkv, g_qkv);
    cudaGetSymbolAddress((void**)&att, g_att);

    // 1. QKV = hs @ W_attn + b_attn   [2048, 3072]
    {
        dim3 grid(N3 / 128, S_LEN / 128);
        sgemm_bias<N3, DMODEL><<<grid, 256>>>(hs, W_attn, b_attn, qkv);
    }
    // 2. Causal attention -> g_att [2048, 1024]
    {
        dim3 grid(S_LEN / 128, NHEAD);
        attn_kernel<<<grid, 128>>>();
    }
    // 3. out = att @ W_proj + b_proj  [2048, 1024]
    {
        dim3 grid(DMODEL / 128, S_LEN / 128);
        sgemm_bias<DMODEL, DMODEL><<<grid, 256>>>(att, W_proj, b_proj, out);
    }
}

// round 5
// speedup vs baseline: 1.4730x; 1.2458x over previous
#include <cuda_runtime.h>
#include <cuda_bf16.h>
#include <cstdint>

#define S_LEN 2048
#define DMODEL 1024
#define NHEAD 16
#define HSZ 64
#define N3 (3 * DMODEL)

typedef __nv_bfloat16 bf16;

// ---------------- scratch (__device__ globals; no allocations) -------------
__device__ float g_qkv[S_LEN * N3];          // fp32 QKV
__device__ bf16 g_ah[S_LEN * DMODEL];        // hidden hi
__device__ bf16 g_al[S_LEN * DMODEL];        // hidden lo
__device__ bf16 g_wth[N3 * DMODEL];          // W_attn^T hi [3072,1024]
__device__ bf16 g_wtl[N3 * DMODEL];          // W_attn^T lo
__device__ bf16 g_pth[DMODEL * DMODEL];      // W_proj^T hi
__device__ bf16 g_ptl[DMODEL * DMODEL];      // W_proj^T lo
__device__ bf16 g_oh[S_LEN * DMODEL];        // attn out hi
__device__ bf16 g_ol[S_LEN * DMODEL];        // attn out lo

// ---------------- PTX helpers (all valid on compute_103, no 'a' features) --
__device__ __forceinline__ uint32_t smem_u32(const void* p) {
    uint32_t a;
    asm("{ .reg .u64 t; cvta.to.shared.u64 t, %1; cvt.u32.u64 %0, t; }"
        : "=r"(a) : "l"(p));
    return a;
}
__device__ __forceinline__ void cp16(uint32_t dst, const void* src) {
    asm volatile("cp.async.cg.shared.global [%0], [%1], 16;"
                 :: "r"(dst), "l"(src) : "memory");
}
__device__ __forceinline__ void cp_commit() {
    asm volatile("cp.async.commit_group;" ::: "memory");
}
__device__ __forceinline__ void ldsm_x4(uint32_t* r, uint32_t a) {
    asm volatile("ldmatrix.sync.aligned.m8n8.x4.shared.b16 {%0,%1,%2,%3}, [%4];"
                 : "=r"(r[0]), "=r"(r[1]), "=r"(r[2]), "=r"(r[3]) : "r"(a));
}
__device__ __forceinline__ void ldsm_x2(uint32_t* r, uint32_t a) {
    asm volatile("ldmatrix.sync.aligned.m8n8.x2.shared.b16 {%0,%1}, [%2];"
                 : "=r"(r[0]), "=r"(r[1]) : "r"(a));
}
__device__ __forceinline__ void mma16816(float* c, const uint32_t* a,
                                         const uint32_t* b) {
    asm volatile(
        "mma.sync.aligned.m16n8k16.row.col.f32.bf16.bf16.f32 "
        "{%0,%1,%2,%3}, {%4,%5,%6,%7}, {%8,%9}, {%0,%1,%2,%3};"
        : "+f"(c[0]), "+f"(c[1]), "+f"(c[2]), "+f"(c[3])
        : "r"(a[0]), "r"(a[1]), "r"(a[2]), "r"(a[3]), "r"(b[0]), "r"(b[1]));
}

// ---------------------------------------------------------------------------
// Precompute 1: fp32 -> (hi, lo) bf16 split, row-major (hidden states)
// ---------------------------------------------------------------------------
__global__ void split_kernel(const float* __restrict__ x,
                             bf16* __restrict__ hi, bf16* __restrict__ lo) {
    const int i = blockIdx.x * blockDim.x + threadIdx.x;  // one float4
    float4 v = ((const float4*)x)[i];
    bf16 h0 = __float2bfloat16(v.x), h1 = __float2bfloat16(v.y);
    bf16 h2 = __float2bfloat16(v.z), h3 = __float2bfloat16(v.w);
    union { __nv_bfloat162 b[2]; uint2 u; } H, L;
    H.b[0] = __nv_bfloat162(h0, h1);
    H.b[1] = __nv_bfloat162(h2, h3);
    L.b[0] = __nv_bfloat162(__float2bfloat16(v.x - __bfloat162float(h0)),
                            __float2bfloat16(v.y - __bfloat162float(h1)));
    L.b[1] = __nv_bfloat162(__float2bfloat16(v.z - __bfloat162float(h2)),
                            __float2bfloat16(v.w - __bfloat162float(h3)));
    ((uint2*)hi)[i] = H.u;
    ((uint2*)lo)[i] = L.u;
}

// ---------------------------------------------------------------------------
// Precompute 2: W [K,N] fp32 -> W^T hi/lo bf16 [N,K]
// ---------------------------------------------------------------------------
__global__ void transpose_split(const float* __restrict__ W,
                                bf16* __restrict__ Th, bf16* __restrict__ Tl,
                                int K, int N) {
    __shared__ float tile[32][33];
    const int n0 = blockIdx.x * 32, k0 = blockIdx.y * 32;
    const int tx = threadIdx.x, ty = threadIdx.y;  // (32, 8)
#pragma unroll
    for (int i = 0; i < 4; i++)
        tile[ty + 8 * i][tx] = W[(size_t)(k0 + ty + 8 * i) * N + n0 + tx];
    __syncthreads();
#pragma unroll
    for (int i = 0; i < 4; i++) {
        const float x = tile[tx][ty + 8 * i];
        const bf16 h = __float2bfloat16(x);
        const size_t o = (size_t)(n0 + ty + 8 * i) * K + k0 + tx;
        Th[o] = h;
        Tl[o] = __float2bfloat16(x - __bfloat162float(h));
    }
}

// ---------------------------------------------------------------------------
// HMMA GEMM: C[M, NDIM] = Ah*Bh^T + Ah*Bl^T + Al*Bh^T + bias
// A: [M, K] bf16 row-major. B: [N, K] bf16 row-major (pre-transposed W).
// CTA 128x128, BK=32, 256 thr = 8 warps (2x4), warp tile 64x32.
// cp.async double-buffered smem, 80B padded rows (conflict-free ldmatrix).
// ---------------------------------------------------------------------------
template <int NDIM, int KDIM>
__global__ __launch_bounds__(256, 1)
void gemm_hmma(const bf16* __restrict__ Ah_, const bf16* __restrict__ Al_,
               const bf16* __restrict__ Bh_, const bf16* __restrict__ Bl_,
               const float* __restrict__ bias, float* __restrict__ C) {
    extern __shared__ __align__(128) char smem[];
    constexpr int TILE = 128 * 80;          // 128 rows x (64B data + 16B pad)
    constexpr int STAGE = 4 * TILE;         // Ah, Al, Bh, Bl
    const int tid = threadIdx.x, lane = tid & 31, wid = tid >> 5;
    const int warp_m = wid & 1, warp_n = wid >> 1;
    const int bx = blockIdx.x, by = blockIdx.y;
    const uint32_t sb = smem_u32(smem);

    const bf16* gsrc[4] = {Ah_ + (size_t)(by * 128) * KDIM,
                           Al_ + (size_t)(by * 128) * KDIM,
                           Bh_ + (size_t)(bx * 128) * KDIM,
                           Bl_ + (size_t)(bx * 128) * KDIM};

    // issue async loads for K-chunk t into stage t&1
    auto issue = [&](int t) {
        const uint32_t stb = sb + (uint32_t)((t & 1) * STAGE);
        const int k0 = t * 32;
#pragma unroll
        for (int tl = 0; tl < 4; tl++) {
#pragma unroll
            for (int i = 0; i < 2; i++) {
                const int c = tid + i * 256;          // 0..511 chunks of 16B
                const int row = c >> 2, cc = c & 3;
                cp16(stb + (uint32_t)(tl * TILE + row * 80 + cc * 16),
                     gsrc[tl] + (size_t)row * KDIM + k0 + cc * 8);
            }
        }
        cp_commit();
    };

    float c[4][4][4];
#pragma unroll
    for (int m = 0; m < 4; m++)
#pragma unroll
        for (int n = 0; n < 4; n++)
#pragma unroll
            for (int k = 0; k < 4; k++) c[m][n][k] = 0.f;

    issue(0);
    constexpr int NT = KDIM / 32;
    for (int t = 0; t < NT; t++) {
        if (t + 1 < NT) {
            issue(t + 1);
            asm volatile("cp.async.wait_group 1;" ::: "memory");
        } else {
            asm volatile("cp.async.wait_group 0;" ::: "memory");
        }
        __syncthreads();
        const uint32_t base = sb + (uint32_t)((t & 1) * STAGE);
#pragma unroll
        for (int ks = 0; ks < 2; ks++) {
            uint32_t ah[4][4], al[4][4], bh[4][2], bl[4][2];
#pragma unroll
            for (int mt = 0; mt < 4; mt++) {
                const int row = warp_m * 64 + mt * 16 + (lane & 15);
                const uint32_t off =
                    (uint32_t)(row * 80 + ks * 32 + (lane >> 4) * 16);
                ldsm_x4(ah[mt], base + 0 * TILE + off);
                ldsm_x4(al[mt], base + 1 * TILE + off);
            }
#pragma unroll
            for (int nt = 0; nt < 4; nt++) {
                const int rowb = warp_n * 32 + nt * 8 + (lane & 7);
                const uint32_t offb =
                    (uint32_t)(rowb * 80 + ks * 32 + ((lane >> 3) & 1) * 16);
                ldsm_x2(bh[nt], base + 2 * TILE + offb);
                ldsm_x2(bl[nt], base + 3 * TILE + offb);
            }
#pragma unroll
            for (int mt = 0; mt < 4; mt++)
#pragma unroll
                for (int nt = 0; nt < 4; nt++) {
                    mma16816(c[mt][nt], ah[mt], bh[nt]);
                    mma16816(c[mt][nt], ah[mt], bl[nt]);
                    mma16816(c[mt][nt], al[mt], bh[nt]);
                }
        }
        __syncthreads();
    }

    // Epilogue: bias add + store. c[mt][nt] = {(r,c0),(r,c0+1),(r+8,c0),(r+8,c0+1)}
#pragma unroll
    for (int mt = 0; mt < 4; mt++) {
        const int row0 = by * 128 + warp_m * 64 + mt * 16 + (lane >> 2);
#pragma unroll
        for (int nt = 0; nt < 4; nt++) {
            const int col = bx * 128 + warp_n * 32 + nt * 8 + (lane & 3) * 2;
            const float b0 = bias[col], b1 = bias[col + 1];
            float2 v0 = make_float2(c[mt][nt][0] + b0, c[mt][nt][1] + b1);
            float2 v1 = make_float2(c[mt][nt][2] + b0, c[mt][nt][3] + b1);
            *(float2*)&C[(size_t)row0 * NDIM + col] = v0;
            *(float2*)&C[(size_t)(row0 + 8) * NDIM + col] = v1;
        }
    }
}

// ---------------------------------------------------------------------------
// Flash causal attention, 2 threads per query row (each owns 32 of 64 dims,
// interleaved in 8-float chunks). Block 256 thr = 128 rows; TN=16 key tile.
// Writes bf16 hi/lo split directly (input to proj GEMM). grid (S/128, H)
// ---------------------------------------------------------------------------
__global__ __launch_bounds__(256, 2)
void attn_kernel() {
    constexpr int ROWS = 128, TN = 16;
    __shared__ __align__(16) float Ks[TN][HSZ];
    __shared__ __align__(16) float Vs[TN][HSZ];

    const int hd = blockIdx.y;
    const int tid = threadIdx.x;
    const int rl = tid >> 1, half = tid & 1;
    const int r = blockIdx.x * ROWS + rl;
    const float scale = rsqrtf((float)S_LEN);  // ref scales by sqrt(S)

    float q[32], acc[32];
    {
        const float* qrow = g_qkv + (size_t)r * N3 + hd * HSZ;
#pragma unroll
        for (int c = 0; c < 4; c++) {
            const int col = (half + 2 * c) * 8;
            float4 a = *(const float4*)(qrow + col);
            float4 b = *(const float4*)(qrow + col + 4);
            q[c * 8 + 0] = a.x * scale; q[c * 8 + 1] = a.y * scale;
            q[c * 8 + 2] = a.z * scale; q[c * 8 + 3] = a.w * scale;
            q[c * 8 + 4] = b.x * scale; q[c * 8 + 5] = b.y * scale;
            q[c * 8 + 6] = b.z * scale; q[c * 8 + 7] = b.w * scale;
        }
    }
#pragma unroll
    for (int d = 0; d < 32; d++) acc[d] = 0.f;
    float mmax = -1e30f, l = 0.f;

    const int kend = blockIdx.x * ROWS + ROWS;
    for (int j0 = 0; j0 < kend; j0 += TN) {
        __syncthreads();
        {   // load K/V tile: TN*64 floats each; 256 thr x 1 float4 each
            const int idx = tid * 4;
            const int kr = idx >> 6, kc = idx & 63;
            const size_t base = (size_t)(j0 + kr) * N3 + hd * HSZ + kc;
            *(float4*)&Ks[kr][kc] = *(const float4*)(g_qkv + base + DMODEL);
            *(float4*)&Vs[kr][kc] = *(const float4*)(g_qkv + base + 2 * DMODEL);
        }
        __syncthreads();

        const int jend = min(TN, r - j0 + 1);
        float s[TN];
#pragma unroll
        for (int j = 0; j < TN; j++) {
            float s0 = 0.f, s1 = 0.f, s2 = 0.f, s3 = 0.f;
#pragma unroll
            for (int d4 = 0; d4 < 8; d4++) {
                const int col = (half + 2 * (d4 >> 1)) * 8 + (d4 & 1) * 4;
                float4 kv = *(const float4*)&Ks[j][col];
                s0 = fmaf(q[d4 * 4 + 0], kv.x, s0);
                s1 = fmaf(q[d4 * 4 + 1], kv.y, s1);
                s2 = fmaf(q[d4 * 4 + 2], kv.z, s2);
                s3 = fmaf(q[d4 * 4 + 3], kv.w, s3);
            }
            const float part = (s0 + s1) + (s2 + s3);
            s[j] = part + __shfl_xor_sync(0xffffffffu, part, 1);
        }
#pragma unroll
        for (int j = 0; j < TN; j++)
            if (j >= jend) s[j] = -1e30f;

        float tm = mmax;
#pragma unroll
        for (int j = 0; j < TN; j++) tm = fmaxf(tm, s[j]);
        const float alpha = __expf(mmax - tm);
        mmax = tm;
        l *= alpha;
#pragma unroll
        for (int d = 0; d < 32; d++) acc[d] *= alpha;

#pragma unroll
        for (int j = 0; j < TN; j++) {
            const float p = __expf(s[j] - mmax);
            l += p;
#pragma unroll
            for (int d4 = 0; d4 < 8; d4++) {
                const int col = (half + 2 * (d4 >> 1)) * 8 + (d4 & 1) * 4;
                float4 vv = *(const float4*)&Vs[j][col];
                acc[d4 * 4 + 0] = fmaf(p, vv.x, acc[d4 * 4 + 0]);
                acc[d4 * 4 + 1] = fmaf(p, vv.y, acc[d4 * 4 + 1]);
                acc[d4 * 4 + 2] = fmaf(p, vv.z, acc[d4 * 4 + 2]);
                acc[d4 * 4 + 3] = fmaf(p, vv.w, acc[d4 * 4 + 3]);
            }
        }
    }

    const float inv = 1.f / l;
#pragma unroll
    for (int c = 0; c < 4; c++) {
        union { __nv_bfloat162 b[4]; uint4 u; } H, L;
#pragma unroll
        for (int p = 0; p < 4; p++) {
            const float x0 = acc[c * 8 + 2 * p + 0] * inv;
            const float x1 = acc[c * 8 + 2 * p + 1] * inv;
            const bf16 h0 = __float2bfloat16(x0);
            const bf16 h1 = __float2bfloat16(x1);
            H.b[p] = __nv_bfloat162(h0, h1);
            L.b[p] = __nv_bfloat162(__float2bfloat16(x0 - __bfloat162float(h0)),
                                    __float2bfloat16(x1 - __bfloat162float(h1)));
        }
        const size_t o = (size_t)r * DMODEL + hd * HSZ + (half + 2 * c) * 8;
        *(uint4*)(g_oh + o) = H.u;
        *(uint4*)(g_ol + o) = L.u;
    }
}

// ---------------------------------------------------------------------------
extern "C" void kernel_launch(void* const* d_in, const int* in_sizes, int n_in,
                              void* d_out, int out_size) {
    const float* hs     = (const float*)d_in[0];
    const float* W_attn = (const float*)d_in[1];
    const float* b_attn = (const float*)d_in[2];
    const float* W_proj = (const float*)d_in[3];
    const float* b_proj = (const float*)d_in[4];
    float* out = (float*)d_out;

    float* qkv;
    bf16 *ah, *al, *wth, *wtl, *pth, *ptl, *oh, *ol;
    cudaGetSymbolAddress((void**)&qkv, g_qkv);
    cudaGetSymbolAddress((void**)&ah, g_ah);
    cudaGetSymbolAddress((void**)&al, g_al);
    cudaGetSymbolAddress((void**)&wth, g_wth);
    cudaGetSymbolAddress((void**)&wtl, g_wtl);
    cudaGetSymbolAddress((void**)&pth, g_pth);
    cudaGetSymbolAddress((void**)&ptl, g_ptl);
    cudaGetSymbolAddress((void**)&oh, g_oh);
    cudaGetSymbolAddress((void**)&ol, g_ol);

    constexpr int GEMM_SMEM = 2 * 4 * 128 * 80;  // 81920 B
    cudaFuncSetAttribute(gemm_hmma<N3, DMODEL>,
                         cudaFuncAttributeMaxDynamicSharedMemorySize, GEMM_SMEM);
    cudaFuncSetAttribute(gemm_hmma<DMODEL, DMODEL>,
                         cudaFuncAttributeMaxDynamicSharedMemorySize, GEMM_SMEM);

    // Precompute: splits + transposed/split weights
    split_kernel<<<(S_LEN * DMODEL / 4) / 256, 256>>>(hs, ah, al);
    transpose_split<<<dim3(N3 / 32, DMODEL / 32), dim3(32, 8)>>>(W_attn, wth, wtl,
                                                                 DMODEL, N3);
    transpose_split<<<dim3(DMODEL / 32, DMODEL / 32), dim3(32, 8)>>>(W_proj, pth, ptl,
                                                                     DMODEL, DMODEL);
    // QKV = hs @ W_attn + b_attn   [2048, 3072]
    gemm_hmma<N3, DMODEL><<<dim3(N3 / 128, S_LEN / 128), 256, GEMM_SMEM>>>(
        ah, al, wth, wtl, b_attn, qkv);
    // Causal attention -> bf16 hi/lo split
    attn_kernel<<<dim3(S_LEN / 128, NHEAD), 256>>>();
    // out = att @ W_proj + b_proj  [2048, 1024]
    gemm_hmma<DMODEL, DMODEL><<<dim3(DMODEL / 128, S_LEN / 128), 256, GEMM_SMEM>>>(
        oh, ol, pth, ptl, b_proj, out);
}

// round 6
// speedup vs baseline: 3.4364x; 2.3329x over previous
#include <cuda_runtime.h>
#include <cuda_bf16.h>
#include <cstdint>

#define S_LEN 2048
#define DMODEL 1024
#define NHEAD 16
#define HSZ 64
#define N3 (3 * DMODEL)

typedef __nv_bfloat16 bf16;

// ---------------- scratch (__device__ globals; no allocations) -------------
__device__ bf16 g_ah[S_LEN * DMODEL];        // hidden hi
__device__ bf16 g_al[S_LEN * DMODEL];        // hidden lo
__device__ bf16 g_wth[N3 * DMODEL];          // W_attn^T hi [3072,1024]
__device__ bf16 g_wtl[N3 * DMODEL];          // W_attn^T lo
__device__ bf16 g_pth[DMODEL * DMODEL];      // W_proj^T hi
__device__ bf16 g_ptl[DMODEL * DMODEL];      // W_proj^T lo
__device__ bf16 g_qkvh[S_LEN * N3];          // QKV hi (GEMM epilogue split)
__device__ bf16 g_qkvl[S_LEN * N3];          // QKV lo
__device__ bf16 g_oh[S_LEN * DMODEL];        // attn out hi
__device__ bf16 g_ol[S_LEN * DMODEL];        // attn out lo

// ---------------- PTX helpers (compute_103-safe, no 'a' features) ----------
__device__ __forceinline__ uint32_t smem_u32(const void* p) {
    uint32_t a;
    asm("{ .reg .u64 t; cvta.to.shared.u64 t, %1; cvt.u32.u64 %0, t; }"
        : "=r"(a) : "l"(p));
    return a;
}
__device__ __forceinline__ void cp16(uint32_t dst, const void* src) {
    asm volatile("cp.async.cg.shared.global [%0], [%1], 16;"
                 :: "r"(dst), "l"(src) : "memory");
}
__device__ __forceinline__ void cp_commit() {
    asm volatile("cp.async.commit_group;" ::: "memory");
}
__device__ __forceinline__ void ldsm_x4(uint32_t* r, uint32_t a) {
    asm volatile("ldmatrix.sync.aligned.m8n8.x4.shared.b16 {%0,%1,%2,%3}, [%4];"
                 : "=r"(r[0]), "=r"(r[1]), "=r"(r[2]), "=r"(r[3]) : "r"(a));
}
__device__ __forceinline__ void ldsm_x2(uint32_t* r, uint32_t a) {
    asm volatile("ldmatrix.sync.aligned.m8n8.x2.shared.b16 {%0,%1}, [%2];"
                 : "=r"(r[0]), "=r"(r[1]) : "r"(a));
}
__device__ __forceinline__ void ldsm_x2t(uint32_t* r, uint32_t a) {
    asm volatile("ldmatrix.sync.aligned.m8n8.x2.trans.shared.b16 {%0,%1}, [%2];"
                 : "=r"(r[0]), "=r"(r[1]) : "r"(a));
}
__device__ __forceinline__ void mma16816(float* c, const uint32_t* a,
                                         const uint32_t* b) {
    asm volatile(
        "mma.sync.aligned.m16n8k16.row.col.f32.bf16.bf16.f32 "
        "{%0,%1,%2,%3}, {%4,%5,%6,%7}, {%8,%9}, {%0,%1,%2,%3};"
        : "+f"(c[0]), "+f"(c[1]), "+f"(c[2]), "+f"(c[3])
        : "r"(a[0]), "r"(a[1]), "r"(a[2]), "r"(a[3]), "r"(b[0]), "r"(b[1]));
}
// fma-pipe exp(x) for x <= 0 (handles -1e30 via clamp); rel err ~2e-6
__device__ __forceinline__ float fexp(float x) {
    float y = fmaxf(x * 1.4426950408889634f, -126.f);
    float z = y + 12582912.f;                       // round-to-nearest-int magic
    int i = __float_as_int(z) - 0x4B400000;
    float f = y - (z - 12582912.f);                 // frac in [-0.5, 0.5]
    float p = 1.3333558146e-3f;
    p = fmaf(p, f, 9.6181291794e-3f);
    p = fmaf(p, f, 5.5504108665e-2f);
    p = fmaf(p, f, 2.4022650696e-1f);
    p = fmaf(p, f, 6.9314718056e-1f);
    p = fmaf(p, f, 1.0f);
    return __int_as_float(__float_as_int(p) + (i << 23));
}
__device__ __forceinline__ uint32_t pack_bf16(float x, float y) {
    __nv_bfloat162 t = __floats2bfloat162_rn(x, y);
    return *(uint32_t*)&t;
}

// ---------------------------------------------------------------------------
// Precompute 1: fp32 -> (hi, lo) bf16 split, row-major (hidden states)
// ---------------------------------------------------------------------------
__global__ void split_kernel(const float* __restrict__ x,
                             bf16* __restrict__ hi, bf16* __restrict__ lo) {
    const int i = blockIdx.x * blockDim.x + threadIdx.x;  // one float4
    float4 v = ((const float4*)x)[i];
    bf16 h0 = __float2bfloat16(v.x), h1 = __float2bfloat16(v.y);
    bf16 h2 = __float2bfloat16(v.z), h3 = __float2bfloat16(v.w);
    union { __nv_bfloat162 b[2]; uint2 u; } H, L;
    H.b[0] = __nv_bfloat162(h0, h1);
    H.b[1] = __nv_bfloat162(h2, h3);
    L.b[0] = __nv_bfloat162(__float2bfloat16(v.x - __bfloat162float(h0)),
                            __float2bfloat16(v.y - __bfloat162float(h1)));
    L.b[1] = __nv_bfloat162(__float2bfloat16(v.z - __bfloat162float(h2)),
                            __float2bfloat16(v.w - __bfloat162float(h3)));
    ((uint2*)hi)[i] = H.u;
    ((uint2*)lo)[i] = L.u;
}

// ---------------------------------------------------------------------------
// Precompute 2: W [K,N] fp32 -> W^T hi/lo bf16 [N,K]
// ---------------------------------------------------------------------------
__global__ void transpose_split(const float* __restrict__ W,
                                bf16* __restrict__ Th, bf16* __restrict__ Tl,
                                int K, int N) {
    __shared__ float tile[32][33];
    const int n0 = blockIdx.x * 32, k0 = blockIdx.y * 32;
    const int tx = threadIdx.x, ty = threadIdx.y;  // (32, 8)
#pragma unroll
    for (int i = 0; i < 4; i++)
        tile[ty + 8 * i][tx] = W[(size_t)(k0 + ty + 8 * i) * N + n0 + tx];
    __syncthreads();
#pragma unroll
    for (int i = 0; i < 4; i++) {
        const float x = tile[tx][ty + 8 * i];
        const bf16 h = __float2bfloat16(x);
        const size_t o = (size_t)(n0 + ty + 8 * i) * K + k0 + tx;
        Th[o] = h;
        Tl[o] = __float2bfloat16(x - __bfloat162float(h));
    }
}

// ---------------------------------------------------------------------------
// HMMA GEMM: C = Ah*Bh^T + Ah*Bl^T + Al*Bh^T + bias
// SPLIT=true: write bf16 hi/lo (Ch, Cl) instead of fp32 C.
// CTA 128x128, BK=32, 8 warps (2x4), warp tile 64x32, cp.async 2-stage.
// ---------------------------------------------------------------------------
template <int NDIM, int KDIM, bool SPLIT>
__global__ __launch_bounds__(256, 1)
void gemm_hmma(const bf16* __restrict__ Ah_, const bf16* __restrict__ Al_,
               const bf16* __restrict__ Bh_, const bf16* __restrict__ Bl_,
               const float* __restrict__ bias, float* __restrict__ C,
               bf16* __restrict__ Ch, bf16* __restrict__ Cl) {
    extern __shared__ __align__(128) char smem[];
    constexpr int TILE = 128 * 80;
    constexpr int STAGE = 4 * TILE;
    const int tid = threadIdx.x, lane = tid & 31, wid = tid >> 5;
    const int warp_m = wid & 1, warp_n = wid >> 1;
    const int bx = blockIdx.x, by = blockIdx.y;
    const uint32_t sb = smem_u32(smem);

    const bf16* gsrc[4] = {Ah_ + (size_t)(by * 128) * KDIM,
                           Al_ + (size_t)(by * 128) * KDIM,
                           Bh_ + (size_t)(bx * 128) * KDIM,
                           Bl_ + (size_t)(bx * 128) * KDIM};

    auto issue = [&](int t) {
        const uint32_t stb = sb + (uint32_t)((t & 1) * STAGE);
        const int k0 = t * 32;
#pragma unroll
        for (int tl = 0; tl < 4; tl++) {
#pragma unroll
            for (int i = 0; i < 2; i++) {
                const int c = tid + i * 256;
                const int row = c >> 2, cc = c & 3;
                cp16(stb + (uint32_t)(tl * TILE + row * 80 + cc * 16),
                     gsrc[tl] + (size_t)row * KDIM + k0 + cc * 8);
            }
        }
        cp_commit();
    };

    float c[4][4][4];
#pragma unroll
    for (int m = 0; m < 4; m++)
#pragma unroll
        for (int n = 0; n < 4; n++)
#pragma unroll
            for (int k = 0; k < 4; k++) c[m][n][k] = 0.f;

    issue(0);
    constexpr int NT = KDIM / 32;
    for (int t = 0; t < NT; t++) {
        if (t + 1 < NT) {
            issue(t + 1);
            asm volatile("cp.async.wait_group 1;" ::: "memory");
        } else {
            asm volatile("cp.async.wait_group 0;" ::: "memory");
        }
        __syncthreads();
        const uint32_t base = sb + (uint32_t)((t & 1) * STAGE);
#pragma unroll
        for (int ks = 0; ks < 2; ks++) {
            uint32_t ah[4][4], al[4][4], bh[4][2], bl[4][2];
#pragma unroll
            for (int mt = 0; mt < 4; mt++) {
                const int row = warp_m * 64 + mt * 16 + (lane & 15);
                const uint32_t off =
                    (uint32_t)(row * 80 + ks * 32 + (lane >> 4) * 16);
                ldsm_x4(ah[mt], base + 0 * TILE + off);
                ldsm_x4(al[mt], base + 1 * TILE + off);
            }
#pragma unroll
            for (int nt = 0; nt < 4; nt++) {
                const int rowb = warp_n * 32 + nt * 8 + (lane & 7);
                const uint32_t offb =
                    (uint32_t)(rowb * 80 + ks * 32 + ((lane >> 3) & 1) * 16);
                ldsm_x2(bh[nt], base + 2 * TILE + offb);
                ldsm_x2(bl[nt], base + 3 * TILE + offb);
            }
#pragma unroll
            for (int mt = 0; mt < 4; mt++)
#pragma unroll
                for (int nt = 0; nt < 4; nt++) {
                    mma16816(c[mt][nt], ah[mt], bh[nt]);
                    mma16816(c[mt][nt], ah[mt], bl[nt]);
                    mma16816(c[mt][nt], al[mt], bh[nt]);
                }
        }
        __syncthreads();
    }

#pragma unroll
    for (int mt = 0; mt < 4; mt++) {
        const int row0 = by * 128 + warp_m * 64 + mt * 16 + (lane >> 2);
#pragma unroll
        for (int nt = 0; nt < 4; nt++) {
            const int col = bx * 128 + warp_n * 32 + nt * 8 + (lane & 3) * 2;
            const float b0 = bias[col], b1 = bias[col + 1];
            const float v00 = c[mt][nt][0] + b0, v01 = c[mt][nt][1] + b1;
            const float v10 = c[mt][nt][2] + b0, v11 = c[mt][nt][3] + b1;
            if (SPLIT) {
                const bf16 h00 = __float2bfloat16(v00), h01 = __float2bfloat16(v01);
                const bf16 h10 = __float2bfloat16(v10), h11 = __float2bfloat16(v11);
                const size_t o0 = (size_t)row0 * NDIM + col;
                const size_t o1 = (size_t)(row0 + 8) * NDIM + col;
                *(__nv_bfloat162*)&Ch[o0] = __nv_bfloat162(h00, h01);
                *(__nv_bfloat162*)&Ch[o1] = __nv_bfloat162(h10, h11);
                *(__nv_bfloat162*)&Cl[o0] = __nv_bfloat162(
                    __float2bfloat16(v00 - __bfloat162float(h00)),
                    __float2bfloat16(v01 - __bfloat162float(h01)));
                *(__nv_bfloat162*)&Cl[o1] = __nv_bfloat162(
                    __float2bfloat16(v10 - __bfloat162float(h10)),
                    __float2bfloat16(v11 - __bfloat162float(h11)));
            } else {
                *(float2*)&C[(size_t)row0 * NDIM + col] = make_float2(v00, v01);
                *(float2*)&C[(size_t)(row0 + 8) * NDIM + col] = make_float2(v10, v11);
            }
        }
    }
}

// ---------------------------------------------------------------------------
// FlashAttention-2 style causal attention, HMMA bf16 hi/lo (3-term) for both
// QK^T and PV. CTA: 1 head x 128 query rows, 8 warps x m16, key tiles of 64.
// Score C-frags reused as PV A-frags; V via ldmatrix.trans.
// grid (16, 16) with heavy blocks first.
// ---------------------------------------------------------------------------
__global__ __launch_bounds__(256, 1)
void attn_flash() {
    extern __shared__ __align__(128) char smem[];
    constexpr int RS = 144;                   // row stride bytes (128B + 16 pad)
    constexpr int QH_OFF = 0, QL_OFF = 128 * RS;
    constexpr int KV_OFF = 2 * 128 * RS;      // 36864
    constexpr int ARR = 64 * RS;              // 9216 per array
    constexpr int KV_STG = 4 * ARR;           // kh, kl, vh, vl

    const int tid = threadIdx.x, lane = tid & 31, wid = tid >> 5;
    const int hd = blockIdx.y;
    const int bx = gridDim.x - 1 - blockIdx.x;   // heavy first
    const uint32_t sb = smem_u32(smem);
    const int rbase = bx * 128 + wid * 16;
    const float scale = rsqrtf((float)S_LEN);    // ref scales by sqrt(S)

    // ---- issue Q loads (128 rows x 64 bf16, hi+lo) ----
    {
        const size_t qg = (size_t)(bx * 128) * N3 + hd * HSZ;
#pragma unroll
        for (int i = 0; i < 4; i++) {
            const int idx = tid + i * 256;       // 0..1023
            const int row = idx >> 3, ch = idx & 7;
            const size_t g = qg + (size_t)row * N3 + ch * 8;
            cp16(sb + QH_OFF + (uint32_t)(row * RS + ch * 16), g_qkvh + g);
            cp16(sb + QL_OFF + (uint32_t)(row * RS + ch * 16), g_qkvl + g);
        }
    }

    // ---- K/V tile loader (64 keys x 64 dims, 4 arrays) ----
    auto issueKV = [&](int t) {
        const int stg = t & 1;
        const int j0 = t * 64;
        const uint32_t kb = sb + KV_OFF + (uint32_t)(stg * KV_STG);
#pragma unroll
        for (int i = 0; i < 2; i++) {
            const int idx = tid + i * 256;       // 0..511
            const int row = idx >> 3, ch = idx & 7;
            const uint32_t so = (uint32_t)(row * RS + ch * 16);
            const size_t gk = (size_t)(j0 + row) * N3 + DMODEL + hd * HSZ + ch * 8;
            const size_t gv = (size_t)(j0 + row) * N3 + 2 * DMODEL + hd * HSZ + ch * 8;
            cp16(kb + 0 * ARR + so, g_qkvh + gk);
            cp16(kb + 1 * ARR + so, g_qkvl + gk);
            cp16(kb + 2 * ARR + so, g_qkvh + gv);
            cp16(kb + 3 * ARR + so, g_qkvl + gv);
        }
        cp_commit();
    };

    issueKV(0);  // commits Q + KV0 together
    asm volatile("cp.async.wait_group 0;" ::: "memory");
    __syncthreads();

    // ---- Q fragments (persistent in registers) ----
    uint32_t qh[4][4], ql[4][4];
#pragma unroll
    for (int ks = 0; ks < 4; ks++) {
        const uint32_t off =
            (uint32_t)((wid * 16 + (lane & 15)) * RS + ks * 32 + (lane >> 4) * 16);
        ldsm_x4(qh[ks], sb + QH_OFF + off);
        ldsm_x4(ql[ks], sb + QL_OFF + off);
    }

    float o[8][4];
#pragma unroll
    for (int nt = 0; nt < 8; nt++)
#pragma unroll
        for (int i = 0; i < 4; i++) o[nt][i] = 0.f;
    float m0 = -1e30f, m1 = -1e30f, l0 = 0.f, l1 = 0.f;

    const int ntiles = 2 * (bx + 1);
    for (int t = 0; t < ntiles; t++) {
        if (t + 1 < ntiles) {
            issueKV(t + 1);
            asm volatile("cp.async.wait_group 1;" ::: "memory");
        } else {
            asm volatile("cp.async.wait_group 0;" ::: "memory");
        }
        __syncthreads();
        const uint32_t kb = sb + KV_OFF + (uint32_t)((t & 1) * KV_STG);

        // ---- S = Q K^T (3-term) ----
        float s[8][4];
#pragma unroll
        for (int nt = 0; nt < 8; nt++)
#pragma unroll
            for (int i = 0; i < 4; i++) s[nt][i] = 0.f;
#pragma unroll
        for (int ks = 0; ks < 4; ks++) {
#pragma unroll
            for (int nt = 0; nt < 8; nt++) {
                uint32_t bh[2], bl[2];
                const uint32_t offb = (uint32_t)((nt * 8 + (lane & 7)) * RS +
                                                 ks * 32 + ((lane >> 3) & 1) * 16);
                ldsm_x2(bh, kb + 0 * ARR + offb);
                ldsm_x2(bl, kb + 1 * ARR + offb);
                mma16816(s[nt], qh[ks], bh);
                mma16816(s[nt], qh[ks], bl);
                mma16816(s[nt], ql[ks], bh);
            }
        }

        // ---- scale + causal mask ----
        const int j0 = t * 64;
#pragma unroll
        for (int nt = 0; nt < 8; nt++)
#pragma unroll
            for (int i = 0; i < 4; i++) s[nt][i] *= scale;
        if (j0 + 63 > rbase) {
            const int r0 = rbase + (lane >> 2), r1 = r0 + 8;
#pragma unroll
            for (int nt = 0; nt < 8; nt++) {
                const int c0 = j0 + nt * 8 + (lane & 3) * 2;
                if (c0 > r0) s[nt][0] = -1e30f;
                if (c0 + 1 > r0) s[nt][1] = -1e30f;
                if (c0 > r1) s[nt][2] = -1e30f;
                if (c0 + 1 > r1) s[nt][3] = -1e30f;
            }
        }

        // ---- online softmax ----
        float rm0 = -1e30f, rm1 = -1e30f;
#pragma unroll
        for (int nt = 0; nt < 8; nt++) {
            rm0 = fmaxf(rm0, fmaxf(s[nt][0], s[nt][1]));
            rm1 = fmaxf(rm1, fmaxf(s[nt][2], s[nt][3]));
        }
        rm0 = fmaxf(rm0, __shfl_xor_sync(0xffffffffu, rm0, 1));
        rm0 = fmaxf(rm0, __shfl_xor_sync(0xffffffffu, rm0, 2));
        rm1 = fmaxf(rm1, __shfl_xor_sync(0xffffffffu, rm1, 1));
        rm1 = fmaxf(rm1, __shfl_xor_sync(0xffffffffu, rm1, 2));
        const float mn0 = fmaxf(m0, rm0), mn1 = fmaxf(m1, rm1);
        const float a0 = fexp(m0 - mn0), a1 = fexp(m1 - mn1);
        m0 = mn0;
        m1 = mn1;
        float ls0 = 0.f, ls1 = 0.f;
#pragma unroll
        for (int nt = 0; nt < 8; nt++) {
            s[nt][0] = fexp(s[nt][0] - m0);
            s[nt][1] = fexp(s[nt][1] - m0);
            s[nt][2] = fexp(s[nt][2] - m1);
            s[nt][3] = fexp(s[nt][3] - m1);
            ls0 += s[nt][0] + s[nt][1];
            ls1 += s[nt][2] + s[nt][3];
        }
        l0 = l0 * a0 + ls0;
        l1 = l1 * a1 + ls1;
#pragma unroll
        for (int nt = 0; nt < 8; nt++) {
            o[nt][0] *= a0;
            o[nt][1] *= a0;
            o[nt][2] *= a1;
            o[nt][3] *= a1;
        }

        // ---- O += P V (3-term; score frags reused as A frags) ----
#pragma unroll
        for (int kk = 0; kk < 4; kk++) {
            uint32_t pah[4], pal[4];
            {
                const float* sA = s[2 * kk];
                const float* sB = s[2 * kk + 1];
                float hA0 = __bfloat162float(__float2bfloat16(sA[0]));
                float hA1 = __bfloat162float(__float2bfloat16(sA[1]));
                float hA2 = __bfloat162float(__float2bfloat16(sA[2]));
                float hA3 = __bfloat162float(__float2bfloat16(sA[3]));
                float hB0 = __bfloat162float(__float2bfloat16(sB[0]));
                float hB1 = __bfloat162float(__float2bfloat16(sB[1]));
                float hB2 = __bfloat162float(__float2bfloat16(sB[2]));
                float hB3 = __bfloat162float(__float2bfloat16(sB[3]));
                pah[0] = pack_bf16(hA0, hA1);
                pah[1] = pack_bf16(hA2, hA3);
                pah[2] = pack_bf16(hB0, hB1);
                pah[3] = pack_bf16(hB2, hB3);
                pal[0] = pack_bf16(sA[0] - hA0, sA[1] - hA1);
                pal[1] = pack_bf16(sA[2] - hA2, sA[3] - hA3);
                pal[2] = pack_bf16(sB[0] - hB0, sB[1] - hB1);
                pal[3] = pack_bf16(sB[2] - hB2, sB[3] - hB3);
            }
#pragma unroll
            for (int nt = 0; nt < 8; nt++) {
                uint32_t bvh[2], bvl[2];
                const uint32_t offv =
                    (uint32_t)((kk * 16 + (lane & 15)) * RS + nt * 16);
                ldsm_x2t(bvh, kb + 2 * ARR + offv);
                ldsm_x2t(bvl, kb + 3 * ARR + offv);
                mma16816(o[nt], pah, bvh);
                mma16816(o[nt], pal, bvh);
                mma16816(o[nt], pah, bvl);
            }
        }
        __syncthreads();
    }

    // ---- finalize: normalize, split hi/lo, store ----
    l0 += __shfl_xor_sync(0xffffffffu, l0, 1);
    l0 += __shfl_xor_sync(0xffffffffu, l0, 2);
    l1 += __shfl_xor_sync(0xffffffffu, l1, 1);
    l1 += __shfl_xor_sync(0xffffffffu, l1, 2);
    const float i0 = 1.f / l0, i1 = 1.f / l1;
    const int r0 = rbase + (lane >> 2);
#pragma unroll
    for (int nt = 0; nt < 8; nt++) {
        const int col = hd * HSZ + nt * 8 + (lane & 3) * 2;
        const float x0 = o[nt][0] * i0, x1 = o[nt][1] * i0;
        const float x2 = o[nt][2] * i1, x3 = o[nt][3] * i1;
        const bf16 h0 = __float2bfloat16(x0), h1 = __float2bfloat16(x1);
        const bf16 h2 = __float2bfloat16(x2), h3 = __float2bfloat16(x3);
        const size_t o0 = (size_t)r0 * DMODEL + col;
        const size_t o1 = (size_t)(r0 + 8) * DMODEL + col;
        *(__nv_bfloat162*)&g_oh[o0] = __nv_bfloat162(h0, h1);
        *(__nv_bfloat162*)&g_oh[o1] = __nv_bfloat162(h2, h3);
        *(__nv_bfloat162*)&g_ol[o0] = __nv_bfloat162(
            __float2bfloat16(x0 - __bfloat162float(h0)),
            __float2bfloat16(x1 - __bfloat162float(h1)));
        *(__nv_bfloat162*)&g_ol[o1] = __nv_bfloat162(
            __float2bfloat16(x2 - __bfloat162float(h2)),
            __float2bfloat16(x3 - __bfloat162float(h3)));
    }
}

// ---------------------------------------------------------------------------
extern "C" void kernel_launch(void* const* d_in, const int* in_sizes, int n_in,
                              void* d_out, int out_size) {
    const float* hs     = (const float*)d_in[0];
    const float* W_attn = (const float*)d_in[1];
    const float* b_attn = (const float*)d_in[2];
    const float* W_proj = (const float*)d_in[3];
    const float* b_proj = (const float*)d_in[4];
    float* out = (float*)d_out;

    bf16 *ah, *al, *wth, *wtl, *pth, *ptl, *qkvh, *qkvl, *oh, *ol;
    cudaGetSymbolAddress((void**)&ah, g_ah);
    cudaGetSymbolAddress((void**)&al, g_al);
    cudaGetSymbolAddress((void**)&wth, g_wth);
    cudaGetSymbolAddress((void**)&wtl, g_wtl);
    cudaGetSymbolAddress((void**)&pth, g_pth);
    cudaGetSymbolAddress((void**)&ptl, g_ptl);
    cudaGetSymbolAddress((void**)&qkvh, g_qkvh);
    cudaGetSymbolAddress((void**)&qkvl, g_qkvl);
    cudaGetSymbolAddress((void**)&oh, g_oh);
    cudaGetSymbolAddress((void**)&ol, g_ol);

    constexpr int GEMM_SMEM = 2 * 4 * 128 * 80;     // 81920
    constexpr int ATTN_SMEM = 2 * 128 * 144 + 2 * 4 * 64 * 144;  // 110592
    cudaFuncSetAttribute(gemm_hmma<N3, DMODEL, true>,
                         cudaFuncAttributeMaxDynamicSharedMemorySize, GEMM_SMEM);
    cudaFuncSetAttribute(gemm_hmma<DMODEL, DMODEL, false>,
                         cudaFuncAttributeMaxDynamicSharedMemorySize, GEMM_SMEM);
    cudaFuncSetAttribute(attn_flash,
                         cudaFuncAttributeMaxDynamicSharedMemorySize, ATTN_SMEM);

    // Precompute: hidden split + transposed/split weights
    split_kernel<<<(S_LEN * DMODEL / 4) / 256, 256>>>(hs, ah, al);
    transpose_split<<<dim3(N3 / 32, DMODEL / 32), dim3(32, 8)>>>(W_attn, wth, wtl,
                                                                 DMODEL, N3);
    transpose_split<<<dim3(DMODEL / 32, DMODEL / 32), dim3(32, 8)>>>(W_proj, pth, ptl,
                                                                     DMODEL, DMODEL);
    // QKV = hs @ W_attn + b_attn  -> bf16 hi/lo
    gemm_hmma<N3, DMODEL, true><<<dim3(N3 / 128, S_LEN / 128), 256, GEMM_SMEM>>>(
        ah, al, wth, wtl, b_attn, nullptr, qkvh, qkvl);
    // Causal flash attention -> bf16 hi/lo
    attn_flash<<<dim3(S_LEN / 128, NHEAD), 256, ATTN_SMEM>>>();
    // out = att @ W_proj + b_proj (fp32)
    gemm_hmma<DMODEL, DMODEL, false><<<dim3(DMODEL / 128, S_LEN / 128), 256, GEMM_SMEM>>>(
        oh, ol, pth, ptl, b_proj, out, nullptr, nullptr);
}